// round 2
// baseline (speedup 1.0000x reference)
#include <cuda_runtime.h>
#include <math.h>

#define DIMC 1024
#define HEADS 16
#define HDIM 64
#define WIN 128
#define SEQ 8192
#define BATCH 4
#define MROWS (BATCH * SEQ)        // 32768
#define MLPH 2048
#define EPSLN 1e-5f

// ---------------- scratch (device globals; no runtime allocation) ----------
__device__ float g_ln[(size_t)MROWS * DIMC];      // LN output (reused for ln1 and ln2)
__device__ float g_qkv[(size_t)MROWS * 3 * DIMC]; // qkv
__device__ float g_attn[(size_t)MROWS * DIMC];    // attention output (B,N,C)
__device__ float g_x2[(size_t)MROWS * DIMC];      // x + attn proj (residual stream)
__device__ float g_g[(size_t)MROWS * MLPH];       // gelu(fc1)

// ---------------- LayerNorm: one block per row, 256 threads ----------------
__global__ void ln_kernel(const float* __restrict__ x, const float* __restrict__ w,
                          const float* __restrict__ b, float* __restrict__ out) {
    __shared__ float s_sum[8], s_sq[8];
    int row = blockIdx.x;
    const float4* xr = reinterpret_cast<const float4*>(x + (size_t)row * DIMC);
    float4 v = xr[threadIdx.x];
    float s = v.x + v.y + v.z + v.w;
    float q = v.x * v.x + v.y * v.y + v.z * v.z + v.w * v.w;
#pragma unroll
    for (int o = 16; o; o >>= 1) {
        s += __shfl_xor_sync(0xffffffffu, s, o);
        q += __shfl_xor_sync(0xffffffffu, q, o);
    }
    int warp = threadIdx.x >> 5, lane = threadIdx.x & 31;
    if (lane == 0) { s_sum[warp] = s; s_sq[warp] = q; }
    __syncthreads();
    float ts = 0.f, tq = 0.f;
#pragma unroll
    for (int i = 0; i < 8; i++) { ts += s_sum[i]; tq += s_sq[i]; }
    float mean = ts * (1.f / DIMC);
    float var = tq * (1.f / DIMC) - mean * mean;
    float rstd = rsqrtf(var + EPSLN);
    float4 wv = reinterpret_cast<const float4*>(w)[threadIdx.x];
    float4 bv = reinterpret_cast<const float4*>(b)[threadIdx.x];
    float4 o4;
    o4.x = (v.x - mean) * rstd * wv.x + bv.x;
    o4.y = (v.y - mean) * rstd * wv.y + bv.y;
    o4.z = (v.z - mean) * rstd * wv.z + bv.z;
    o4.w = (v.w - mean) * rstd * wv.w + bv.w;
    reinterpret_cast<float4*>(out + (size_t)row * DIMC)[threadIdx.x] = o4;
}

// ---------------- SGEMM: C[M,N] = A[M,K] @ W[N,K]^T + bias (+epilogue) -----
// EPI: 0 = bias only, 1 = bias + exact GELU, 2 = bias + residual
template <int EPI>
__global__ __launch_bounds__(256)
void gemm_kernel(const float* __restrict__ A, const float* __restrict__ W,
                 const float* __restrict__ bias, const float* __restrict__ res,
                 float* __restrict__ C, int M, int N, int K) {
    __shared__ float As[16][132];
    __shared__ float Bs[16][132];
    int tid = threadIdx.x;
    int tx = tid & 15, ty = tid >> 4;
    int m0 = blockIdx.y * 128, n0 = blockIdx.x * 128;

    const float* Ab = A + (size_t)m0 * K;
    const float* Wb = W + (size_t)n0 * K;

    float acc[8][8];
#pragma unroll
    for (int i = 0; i < 8; i++)
#pragma unroll
        for (int j = 0; j < 8; j++) acc[i][j] = 0.f;

    for (int k0 = 0; k0 < K; k0 += 16) {
#pragma unroll
        for (int i = 0; i < 2; i++) {
            int flat = tid + i * 256;          // 0..511
            int row = flat >> 2;               // 0..127
            int kq = (flat & 3) << 2;          // 0,4,8,12
            float4 av = *reinterpret_cast<const float4*>(Ab + (size_t)row * K + k0 + kq);
            As[kq + 0][row] = av.x; As[kq + 1][row] = av.y;
            As[kq + 2][row] = av.z; As[kq + 3][row] = av.w;
            float4 bv = *reinterpret_cast<const float4*>(Wb + (size_t)row * K + k0 + kq);
            Bs[kq + 0][row] = bv.x; Bs[kq + 1][row] = bv.y;
            Bs[kq + 2][row] = bv.z; Bs[kq + 3][row] = bv.w;
        }
        __syncthreads();
#pragma unroll
        for (int kk = 0; kk < 16; kk++) {
            float a[8], bb[8];
            const float4* ap = reinterpret_cast<const float4*>(&As[kk][ty * 8]);
            float4 a0 = ap[0], a1 = ap[1];
            a[0] = a0.x; a[1] = a0.y; a[2] = a0.z; a[3] = a0.w;
            a[4] = a1.x; a[5] = a1.y; a[6] = a1.z; a[7] = a1.w;
            const float4* bp = reinterpret_cast<const float4*>(&Bs[kk][tx * 8]);
            float4 b0 = bp[0], b1 = bp[1];
            bb[0] = b0.x; bb[1] = b0.y; bb[2] = b0.z; bb[3] = b0.w;
            bb[4] = b1.x; bb[5] = b1.y; bb[6] = b1.z; bb[7] = b1.w;
#pragma unroll
            for (int i = 0; i < 8; i++)
#pragma unroll
                for (int j = 0; j < 8; j++) acc[i][j] += a[i] * bb[j];
        }
        __syncthreads();
    }

#pragma unroll
    for (int i = 0; i < 8; i++) {
        int r = m0 + ty * 8 + i;
        float* crow = C + (size_t)r * N + n0 + tx * 8;
        const float* rrow = (EPI == 2) ? (res + (size_t)r * N + n0 + tx * 8) : nullptr;
        float vals[8];
#pragma unroll
        for (int j = 0; j < 8; j++) {
            float v = acc[i][j] + bias[n0 + tx * 8 + j];
            if (EPI == 1) v = 0.5f * v * (1.0f + erff(v * 0.70710678118654752f));
            if (EPI == 2) v += rrow[j];
            vals[j] = v;
        }
        float4 o0 = make_float4(vals[0], vals[1], vals[2], vals[3]);
        float4 o1 = make_float4(vals[4], vals[5], vals[6], vals[7]);
        reinterpret_cast<float4*>(crow)[0] = o0;
        reinterpret_cast<float4*>(crow)[1] = o1;
    }
}

// ---------------- Windowed attention -----------------------------------------
// grid (W=64, H=16, B=4), 128 threads: thread = one query row of the window.
// K/V streamed through SMEM in two 64-row chunks; online softmax.
__global__ __launch_bounds__(128)
void attn_kernel(const float* __restrict__ qkv, float* __restrict__ out) {
    __shared__ float ks[64 * 64];
    __shared__ float vs[64 * 64];
    int w = blockIdx.x, h = blockIdx.y, b = blockIdx.z;
    int q = threadIdx.x;
    size_t rowbase = ((size_t)b * SEQ + (size_t)w * WIN);

    const float4* qrow = reinterpret_cast<const float4*>(
        qkv + (rowbase + q) * (3 * DIMC) + h * HDIM);
    float4 qv[16];
#pragma unroll
    for (int i = 0; i < 16; i++) qv[i] = qrow[i];

    float m = -1e30f, l = 0.f;
    float4 acc[16];
#pragma unroll
    for (int i = 0; i < 16; i++) acc[i] = make_float4(0.f, 0.f, 0.f, 0.f);

    for (int c = 0; c < 2; c++) {
        __syncthreads();
        {
            int r = threadIdx.x >> 1;
            int part = threadIdx.x & 1;
            const float4* krow = reinterpret_cast<const float4*>(
                qkv + (rowbase + c * 64 + r) * (3 * DIMC) + DIMC + h * HDIM + part * 32);
            const float4* vrow = reinterpret_cast<const float4*>(
                qkv + (rowbase + c * 64 + r) * (3 * DIMC) + 2 * DIMC + h * HDIM + part * 32);
            float4* kd = reinterpret_cast<float4*>(&ks[r * 64 + part * 32]);
            float4* vd = reinterpret_cast<float4*>(&vs[r * 64 + part * 32]);
#pragma unroll
            for (int i = 0; i < 8; i++) { kd[i] = krow[i]; vd[i] = vrow[i]; }
        }
        __syncthreads();

        for (int j = 0; j < 64; j++) {
            const float4* kj = reinterpret_cast<const float4*>(&ks[j * 64]);
            float s = 0.f;
#pragma unroll
            for (int i = 0; i < 16; i++) {
                float4 kk = kj[i];
                s += qv[i].x * kk.x + qv[i].y * kk.y + qv[i].z * kk.z + qv[i].w * kk.w;
            }
            s *= 0.125f;  // D^-0.5 with D=64
            float mn = fmaxf(m, s);
            float corr = __expf(m - mn);
            float p = __expf(s - mn);
            l = l * corr + p;
            const float4* vj = reinterpret_cast<const float4*>(&vs[j * 64]);
#pragma unroll
            for (int i = 0; i < 16; i++) {
                float4 vv = vj[i];
                acc[i].x = acc[i].x * corr + p * vv.x;
                acc[i].y = acc[i].y * corr + p * vv.y;
                acc[i].z = acc[i].z * corr + p * vv.z;
                acc[i].w = acc[i].w * corr + p * vv.w;
            }
            m = mn;
        }
    }

    float inv = 1.f / l;
    float4* orow = reinterpret_cast<float4*>(out + (rowbase + q) * DIMC + h * HDIM);
#pragma unroll
    for (int i = 0; i < 16; i++) {
        float4 o = acc[i];
        o.x *= inv; o.y *= inv; o.z *= inv; o.w *= inv;
        orow[i] = o;
    }
}

// ---------------- launch --------------------------------------------------
extern "C" void kernel_launch(void* const* d_in, const int* in_sizes, int n_in,
                              void* d_out, int out_size) {
    const float* x      = (const float*)d_in[0];
    const float* ln1_w  = (const float*)d_in[1];
    const float* ln1_b  = (const float*)d_in[2];
    const float* qkv_w  = (const float*)d_in[3];
    const float* qkv_b  = (const float*)d_in[4];
    const float* proj_w = (const float*)d_in[5];
    const float* proj_b = (const float*)d_in[6];
    const float* ln2_w  = (const float*)d_in[7];
    const float* ln2_b  = (const float*)d_in[8];
    const float* fc1_w  = (const float*)d_in[9];
    const float* fc1_b  = (const float*)d_in[10];
    const float* fc2_w  = (const float*)d_in[11];
    const float* fc2_b  = (const float*)d_in[12];
    float* out = (float*)d_out;

    float *p_ln, *p_qkv, *p_attn, *p_x2, *p_g;
    cudaGetSymbolAddress((void**)&p_ln, g_ln);
    cudaGetSymbolAddress((void**)&p_qkv, g_qkv);
    cudaGetSymbolAddress((void**)&p_attn, g_attn);
    cudaGetSymbolAddress((void**)&p_x2, g_x2);
    cudaGetSymbolAddress((void**)&p_g, g_g);

    // 1. LN1
    ln_kernel<<<MROWS, 256>>>(x, ln1_w, ln1_b, p_ln);

    // 2. QKV: (32768 x 3072) = ln @ qkv_w^T + qkv_b
    {
        dim3 grid(3 * DIMC / 128, MROWS / 128);
        gemm_kernel<0><<<grid, 256>>>(p_ln, qkv_w, qkv_b, nullptr, p_qkv,
                                      MROWS, 3 * DIMC, DIMC);
    }

    // 3. Windowed attention
    {
        dim3 grid(SEQ / WIN, HEADS, BATCH);
        attn_kernel<<<grid, 128>>>(p_qkv, p_attn);
    }

    // 4. Proj + residual: x2 = x + attn @ proj_w^T + proj_b
    {
        dim3 grid(DIMC / 128, MROWS / 128);
        gemm_kernel<2><<<grid, 256>>>(p_attn, proj_w, proj_b, x, p_x2,
                                      MROWS, DIMC, DIMC);
    }

    // 5. LN2
    ln_kernel<<<MROWS, 256>>>(p_x2, ln2_w, ln2_b, p_ln);

    // 6. FC1 + GELU: g = gelu(ln2 @ fc1_w^T + fc1_b)
    {
        dim3 grid(MLPH / 128, MROWS / 128);
        gemm_kernel<1><<<grid, 256>>>(p_ln, fc1_w, fc1_b, nullptr, p_g,
                                      MROWS, MLPH, DIMC);
    }

    // 7. FC2 + residual: out = x2 + g @ fc2_w^T + fc2_b
    {
        dim3 grid(DIMC / 128, MROWS / 128);
        gemm_kernel<2><<<grid, 256>>>(p_g, fc2_w, fc2_b, p_x2, out,
                                      MROWS, DIMC, MLPH);
    }
}

// round 3
// speedup vs baseline: 1.7632x; 1.7632x over previous
#include <cuda_runtime.h>
#include <math.h>

#define DIMC 1024
#define HEADS 16
#define HDIM 64
#define WIN 128
#define SEQ 8192
#define BATCH 4
#define MROWS (BATCH * SEQ)        // 32768
#define MLPH 2048
#define EPSLN 1e-5f

// ---------------- scratch (device globals; no runtime allocation) ----------
__device__ float g_ln[(size_t)MROWS * DIMC];      // LN output (reused)
__device__ float g_qkv[(size_t)MROWS * 3 * DIMC]; // qkv
__device__ float g_attn[(size_t)MROWS * DIMC];    // attention output (B,N,C)
__device__ float g_x2[(size_t)MROWS * DIMC];      // x + attn proj
__device__ float g_g[(size_t)MROWS * MLPH];       // gelu(fc1)

// ---------------- LayerNorm ----------------
__global__ void ln_kernel(const float* __restrict__ x, const float* __restrict__ w,
                          const float* __restrict__ b, float* __restrict__ out) {
    __shared__ float s_sum[8], s_sq[8];
    int row = blockIdx.x;
    const float4* xr = reinterpret_cast<const float4*>(x + (size_t)row * DIMC);
    float4 v = xr[threadIdx.x];
    float s = v.x + v.y + v.z + v.w;
    float q = v.x * v.x + v.y * v.y + v.z * v.z + v.w * v.w;
#pragma unroll
    for (int o = 16; o; o >>= 1) {
        s += __shfl_xor_sync(0xffffffffu, s, o);
        q += __shfl_xor_sync(0xffffffffu, q, o);
    }
    int warp = threadIdx.x >> 5, lane = threadIdx.x & 31;
    if (lane == 0) { s_sum[warp] = s; s_sq[warp] = q; }
    __syncthreads();
    float ts = 0.f, tq = 0.f;
#pragma unroll
    for (int i = 0; i < 8; i++) { ts += s_sum[i]; tq += s_sq[i]; }
    float mean = ts * (1.f / DIMC);
    float var = tq * (1.f / DIMC) - mean * mean;
    float rstd = rsqrtf(var + EPSLN);
    float4 wv = reinterpret_cast<const float4*>(w)[threadIdx.x];
    float4 bv = reinterpret_cast<const float4*>(b)[threadIdx.x];
    float4 o4;
    o4.x = (v.x - mean) * rstd * wv.x + bv.x;
    o4.y = (v.y - mean) * rstd * wv.y + bv.y;
    o4.z = (v.z - mean) * rstd * wv.z + bv.z;
    o4.w = (v.w - mean) * rstd * wv.w + bv.w;
    reinterpret_cast<float4*>(out + (size_t)row * DIMC)[threadIdx.x] = o4;
}

// ---------------- TF32 tensor-core GEMM ------------------------------------
// C[M,N] = A[M,K] @ W[N,K]^T + bias (+epilogue)
// EPI: 0 = bias only, 1 = bias + exact GELU, 2 = bias + residual
// Block tile 128x128x32, 8 warps (2x4), warp tile 64x32, double-buffered SMEM.

__device__ __forceinline__ unsigned f2tf32(float x) {
    unsigned r;
    asm("cvt.rna.tf32.f32 %0, %1;" : "=r"(r) : "f"(x));
    return r;
}

#define SLD 132  // smem row stride (128 + 4 pad)

template <int EPI>
__global__ __launch_bounds__(256)
void mma_gemm(const float* __restrict__ A, const float* __restrict__ W,
              const float* __restrict__ bias, const float* __restrict__ res,
              float* __restrict__ C, int M, int N, int K) {
    extern __shared__ unsigned smem[];
    unsigned* AsBase = smem;                 // [2][32][SLD]
    unsigned* BsBase = smem + 2 * 32 * SLD;  // [2][32][SLD]

    const int tid = threadIdx.x;
    const int lane = tid & 31, warp = tid >> 5;
    const int warp_m = warp >> 2, warp_n = warp & 3;
    const int grp = lane >> 2, tig = lane & 3;
    const int m0 = blockIdx.y * 128, n0 = blockIdx.x * 128;

    const float* Ab = A + (size_t)m0 * K;
    const float* Wb = W + (size_t)n0 * K;

    float acc[4][4][4];
#pragma unroll
    for (int mt = 0; mt < 4; mt++)
#pragma unroll
        for (int nt = 0; nt < 4; nt++)
#pragma unroll
            for (int i = 0; i < 4; i++) acc[mt][nt][i] = 0.f;

    float4 ra[4], rb[4];

    // ---- prefetch tile 0 into regs ----
#pragma unroll
    for (int i = 0; i < 4; i++) {
        int flat = tid + i * 256;
        int row = flat >> 3, kq = (flat & 7) << 2;
        ra[i] = *reinterpret_cast<const float4*>(Ab + (size_t)row * K + kq);
        rb[i] = *reinterpret_cast<const float4*>(Wb + (size_t)row * K + kq);
    }
    // ---- store tile 0 (converted to tf32) ----
#pragma unroll
    for (int i = 0; i < 4; i++) {
        int flat = tid + i * 256;
        int row = flat >> 3, kq = (flat & 7) << 2;
        unsigned* as = AsBase;
        unsigned* bs = BsBase;
        as[(kq + 0) * SLD + row] = f2tf32(ra[i].x);
        as[(kq + 1) * SLD + row] = f2tf32(ra[i].y);
        as[(kq + 2) * SLD + row] = f2tf32(ra[i].z);
        as[(kq + 3) * SLD + row] = f2tf32(ra[i].w);
        bs[(kq + 0) * SLD + row] = f2tf32(rb[i].x);
        bs[(kq + 1) * SLD + row] = f2tf32(rb[i].y);
        bs[(kq + 2) * SLD + row] = f2tf32(rb[i].z);
        bs[(kq + 3) * SLD + row] = f2tf32(rb[i].w);
    }
    __syncthreads();

    const int KIT = K >> 5;  // K/32
    for (int it = 0; it < KIT; ++it) {
        if (it + 1 < KIT) {
            int k0 = (it + 1) << 5;
#pragma unroll
            for (int i = 0; i < 4; i++) {
                int flat = tid + i * 256;
                int row = flat >> 3, kq = (flat & 7) << 2;
                ra[i] = *reinterpret_cast<const float4*>(Ab + (size_t)row * K + k0 + kq);
                rb[i] = *reinterpret_cast<const float4*>(Wb + (size_t)row * K + k0 + kq);
            }
        }

        const unsigned* as = AsBase + (it & 1) * 32 * SLD;
        const unsigned* bs = BsBase + (it & 1) * 32 * SLD;

#pragma unroll
        for (int ks = 0; ks < 4; ks++) {
            int kb = ks * 8;
            unsigned af[4][4], bf[4][2];
#pragma unroll
            for (int mt = 0; mt < 4; mt++) {
                int am = warp_m * 64 + mt * 16 + grp;
                af[mt][0] = as[(kb + tig) * SLD + am];
                af[mt][1] = as[(kb + tig) * SLD + am + 8];
                af[mt][2] = as[(kb + tig + 4) * SLD + am];
                af[mt][3] = as[(kb + tig + 4) * SLD + am + 8];
            }
#pragma unroll
            for (int nt = 0; nt < 4; nt++) {
                int bn = warp_n * 32 + nt * 8 + grp;
                bf[nt][0] = bs[(kb + tig) * SLD + bn];
                bf[nt][1] = bs[(kb + tig + 4) * SLD + bn];
            }
#pragma unroll
            for (int mt = 0; mt < 4; mt++)
#pragma unroll
                for (int nt = 0; nt < 4; nt++) {
                    asm volatile(
                        "mma.sync.aligned.m16n8k8.row.col.f32.tf32.tf32.f32 "
                        "{%0,%1,%2,%3}, {%4,%5,%6,%7}, {%8,%9}, {%0,%1,%2,%3};"
                        : "+f"(acc[mt][nt][0]), "+f"(acc[mt][nt][1]),
                          "+f"(acc[mt][nt][2]), "+f"(acc[mt][nt][3])
                        : "r"(af[mt][0]), "r"(af[mt][1]), "r"(af[mt][2]), "r"(af[mt][3]),
                          "r"(bf[nt][0]), "r"(bf[nt][1]));
                }
        }

        if (it + 1 < KIT) {
            unsigned* asn = AsBase + ((it + 1) & 1) * 32 * SLD;
            unsigned* bsn = BsBase + ((it + 1) & 1) * 32 * SLD;
#pragma unroll
            for (int i = 0; i < 4; i++) {
                int flat = tid + i * 256;
                int row = flat >> 3, kq = (flat & 7) << 2;
                asn[(kq + 0) * SLD + row] = f2tf32(ra[i].x);
                asn[(kq + 1) * SLD + row] = f2tf32(ra[i].y);
                asn[(kq + 2) * SLD + row] = f2tf32(ra[i].z);
                asn[(kq + 3) * SLD + row] = f2tf32(ra[i].w);
                bsn[(kq + 0) * SLD + row] = f2tf32(rb[i].x);
                bsn[(kq + 1) * SLD + row] = f2tf32(rb[i].y);
                bsn[(kq + 2) * SLD + row] = f2tf32(rb[i].z);
                bsn[(kq + 3) * SLD + row] = f2tf32(rb[i].w);
            }
            __syncthreads();
        }
    }

    // ---- epilogue ----
#pragma unroll
    for (int mt = 0; mt < 4; mt++) {
#pragma unroll
        for (int half = 0; half < 2; half++) {
            int r = m0 + warp_m * 64 + mt * 16 + grp + half * 8;
#pragma unroll
            for (int nt = 0; nt < 4; nt++) {
                int c = n0 + warp_n * 32 + nt * 8 + tig * 2;
                float v0 = acc[mt][nt][half * 2 + 0] + __ldg(&bias[c]);
                float v1 = acc[mt][nt][half * 2 + 1] + __ldg(&bias[c + 1]);
                if (EPI == 1) {
                    v0 = 0.5f * v0 * (1.0f + erff(v0 * 0.70710678118654752f));
                    v1 = 0.5f * v1 * (1.0f + erff(v1 * 0.70710678118654752f));
                }
                if (EPI == 2) {
                    const float2 rr = *reinterpret_cast<const float2*>(res + (size_t)r * N + c);
                    v0 += rr.x; v1 += rr.y;
                }
                *reinterpret_cast<float2*>(C + (size_t)r * N + c) = make_float2(v0, v1);
            }
        }
    }
}

// ---------------- Windowed attention (fp32, unchanged) ---------------------
__global__ __launch_bounds__(128)
void attn_kernel(const float* __restrict__ qkv, float* __restrict__ out) {
    __shared__ float ks[64 * 64];
    __shared__ float vs[64 * 64];
    int w = blockIdx.x, h = blockIdx.y, b = blockIdx.z;
    int q = threadIdx.x;
    size_t rowbase = ((size_t)b * SEQ + (size_t)w * WIN);

    const float4* qrow = reinterpret_cast<const float4*>(
        qkv + (rowbase + q) * (3 * DIMC) + h * HDIM);
    float4 qv[16];
#pragma unroll
    for (int i = 0; i < 16; i++) qv[i] = qrow[i];

    float m = -1e30f, l = 0.f;
    float4 acc[16];
#pragma unroll
    for (int i = 0; i < 16; i++) acc[i] = make_float4(0.f, 0.f, 0.f, 0.f);

    for (int c = 0; c < 2; c++) {
        __syncthreads();
        {
            int r = threadIdx.x >> 1;
            int part = threadIdx.x & 1;
            const float4* krow = reinterpret_cast<const float4*>(
                qkv + (rowbase + c * 64 + r) * (3 * DIMC) + DIMC + h * HDIM + part * 32);
            const float4* vrow = reinterpret_cast<const float4*>(
                qkv + (rowbase + c * 64 + r) * (3 * DIMC) + 2 * DIMC + h * HDIM + part * 32);
            float4* kd = reinterpret_cast<float4*>(&ks[r * 64 + part * 32]);
            float4* vd = reinterpret_cast<float4*>(&vs[r * 64 + part * 32]);
#pragma unroll
            for (int i = 0; i < 8; i++) { kd[i] = krow[i]; vd[i] = vrow[i]; }
        }
        __syncthreads();

        for (int j = 0; j < 64; j++) {
            const float4* kj = reinterpret_cast<const float4*>(&ks[j * 64]);
            float s = 0.f;
#pragma unroll
            for (int i = 0; i < 16; i++) {
                float4 kk = kj[i];
                s += qv[i].x * kk.x + qv[i].y * kk.y + qv[i].z * kk.z + qv[i].w * kk.w;
            }
            s *= 0.125f;
            float mn = fmaxf(m, s);
            float corr = __expf(m - mn);
            float p = __expf(s - mn);
            l = l * corr + p;
            const float4* vj = reinterpret_cast<const float4*>(&vs[j * 64]);
#pragma unroll
            for (int i = 0; i < 16; i++) {
                float4 vv = vj[i];
                acc[i].x = acc[i].x * corr + p * vv.x;
                acc[i].y = acc[i].y * corr + p * vv.y;
                acc[i].z = acc[i].z * corr + p * vv.z;
                acc[i].w = acc[i].w * corr + p * vv.w;
            }
            m = mn;
        }
    }

    float inv = 1.f / l;
    float4* orow = reinterpret_cast<float4*>(out + (rowbase + q) * DIMC + h * HDIM);
#pragma unroll
    for (int i = 0; i < 16; i++) {
        float4 o = acc[i];
        o.x *= inv; o.y *= inv; o.z *= inv; o.w *= inv;
        orow[i] = o;
    }
}

// ---------------- launch --------------------------------------------------
#define GEMM_SMEM (4 * 32 * SLD * 4)  // 2 buffers * (As+Bs) * 32 * SLD * 4B

extern "C" void kernel_launch(void* const* d_in, const int* in_sizes, int n_in,
                              void* d_out, int out_size) {
    const float* x      = (const float*)d_in[0];
    const float* ln1_w  = (const float*)d_in[1];
    const float* ln1_b  = (const float*)d_in[2];
    const float* qkv_w  = (const float*)d_in[3];
    const float* qkv_b  = (const float*)d_in[4];
    const float* proj_w = (const float*)d_in[5];
    const float* proj_b = (const float*)d_in[6];
    const float* ln2_w  = (const float*)d_in[7];
    const float* ln2_b  = (const float*)d_in[8];
    const float* fc1_w  = (const float*)d_in[9];
    const float* fc1_b  = (const float*)d_in[10];
    const float* fc2_w  = (const float*)d_in[11];
    const float* fc2_b  = (const float*)d_in[12];
    float* out = (float*)d_out;

    float *p_ln, *p_qkv, *p_attn, *p_x2, *p_g;
    cudaGetSymbolAddress((void**)&p_ln, g_ln);
    cudaGetSymbolAddress((void**)&p_qkv, g_qkv);
    cudaGetSymbolAddress((void**)&p_attn, g_attn);
    cudaGetSymbolAddress((void**)&p_x2, g_x2);
    cudaGetSymbolAddress((void**)&p_g, g_g);

    static bool attr_done = false;
    if (!attr_done) {
        cudaFuncSetAttribute(mma_gemm<0>, cudaFuncAttributeMaxDynamicSharedMemorySize, GEMM_SMEM);
        cudaFuncSetAttribute(mma_gemm<1>, cudaFuncAttributeMaxDynamicSharedMemorySize, GEMM_SMEM);
        cudaFuncSetAttribute(mma_gemm<2>, cudaFuncAttributeMaxDynamicSharedMemorySize, GEMM_SMEM);
        attr_done = true;
    }

    // 1. LN1
    ln_kernel<<<MROWS, 256>>>(x, ln1_w, ln1_b, p_ln);

    // 2. QKV
    {
        dim3 grid(3 * DIMC / 128, MROWS / 128);
        mma_gemm<0><<<grid, 256, GEMM_SMEM>>>(p_ln, qkv_w, qkv_b, nullptr, p_qkv,
                                              MROWS, 3 * DIMC, DIMC);
    }

    // 3. Windowed attention
    {
        dim3 grid(SEQ / WIN, HEADS, BATCH);
        attn_kernel<<<grid, 128>>>(p_qkv, p_attn);
    }

    // 4. Proj + residual
    {
        dim3 grid(DIMC / 128, MROWS / 128);
        mma_gemm<2><<<grid, 256, GEMM_SMEM>>>(p_attn, proj_w, proj_b, x, p_x2,
                                              MROWS, DIMC, DIMC);
    }

    // 5. LN2
    ln_kernel<<<MROWS, 256>>>(p_x2, ln2_w, ln2_b, p_ln);

    // 6. FC1 + GELU
    {
        dim3 grid(MLPH / 128, MROWS / 128);
        mma_gemm<1><<<grid, 256, GEMM_SMEM>>>(p_ln, fc1_w, fc1_b, nullptr, p_g,
                                              MROWS, MLPH, DIMC);
    }

    // 7. FC2 + residual
    {
        dim3 grid(DIMC / 128, MROWS / 128);
        mma_gemm<2><<<grid, 256, GEMM_SMEM>>>(p_g, fc2_w, fc2_b, p_x2, out,
                                              MROWS, DIMC, MLPH);
    }
}

// round 4
// speedup vs baseline: 4.1699x; 2.3650x over previous
#include <cuda_runtime.h>
#include <cuda_fp16.h>
#include <math.h>

#define DIMC 1024
#define HEADS 16
#define HDIM 64
#define WIN 128
#define SEQ 8192
#define BATCH 4
#define MROWS (BATCH * SEQ)        // 32768
#define MLPH 2048
#define EPSLN 1e-5f

// ---------------- scratch (device globals; no runtime allocation) ----------
__device__ __half g_ln[(size_t)MROWS * DIMC];       // LN output (half, reused)
__device__ __half g_qkv[(size_t)MROWS * 3 * DIMC];  // qkv (half)
__device__ __half g_attn[(size_t)MROWS * DIMC];     // attention output (half)
__device__ float  g_x2[(size_t)MROWS * DIMC];       // residual stream (fp32)
__device__ __half g_g[(size_t)MROWS * MLPH];        // gelu(fc1) (half)
// half weights (converted each call)
__device__ __half g_wqkv[(size_t)3 * DIMC * DIMC];
__device__ __half g_wproj[(size_t)DIMC * DIMC];
__device__ __half g_wfc1[(size_t)MLPH * DIMC];
__device__ __half g_wfc2[(size_t)DIMC * MLPH];

// ---------------- fp32 -> fp16 converter -----------------------------------
__global__ void f2h_kernel(const float* __restrict__ src, __half* __restrict__ dst, int n4) {
    int i = blockIdx.x * blockDim.x + threadIdx.x;
    if (i < n4) {
        float4 v = reinterpret_cast<const float4*>(src)[i];
        __half2 h0 = __floats2half2_rn(v.x, v.y);
        __half2 h1 = __floats2half2_rn(v.z, v.w);
        reinterpret_cast<__half2*>(dst)[2 * i] = h0;
        reinterpret_cast<__half2*>(dst)[2 * i + 1] = h1;
    }
}

// ---------------- LayerNorm (fp32 in, half out) ----------------------------
__global__ void ln_kernel(const float* __restrict__ x, const float* __restrict__ w,
                          const float* __restrict__ b, __half* __restrict__ out) {
    __shared__ float s_sum[8], s_sq[8];
    int row = blockIdx.x;
    const float4* xr = reinterpret_cast<const float4*>(x + (size_t)row * DIMC);
    float4 v = xr[threadIdx.x];
    float s = v.x + v.y + v.z + v.w;
    float q = v.x * v.x + v.y * v.y + v.z * v.z + v.w * v.w;
#pragma unroll
    for (int o = 16; o; o >>= 1) {
        s += __shfl_xor_sync(0xffffffffu, s, o);
        q += __shfl_xor_sync(0xffffffffu, q, o);
    }
    int warp = threadIdx.x >> 5, lane = threadIdx.x & 31;
    if (lane == 0) { s_sum[warp] = s; s_sq[warp] = q; }
    __syncthreads();
    float ts = 0.f, tq = 0.f;
#pragma unroll
    for (int i = 0; i < 8; i++) { ts += s_sum[i]; tq += s_sq[i]; }
    float mean = ts * (1.f / DIMC);
    float var = tq * (1.f / DIMC) - mean * mean;
    float rstd = rsqrtf(var + EPSLN);
    float4 wv = reinterpret_cast<const float4*>(w)[threadIdx.x];
    float4 bv = reinterpret_cast<const float4*>(b)[threadIdx.x];
    __half2 h0 = __floats2half2_rn((v.x - mean) * rstd * wv.x + bv.x,
                                   (v.y - mean) * rstd * wv.y + bv.y);
    __half2 h1 = __floats2half2_rn((v.z - mean) * rstd * wv.z + bv.z,
                                   (v.w - mean) * rstd * wv.w + bv.w);
    reinterpret_cast<__half2*>(out + (size_t)row * DIMC)[2 * threadIdx.x] = h0;
    reinterpret_cast<__half2*>(out + (size_t)row * DIMC)[2 * threadIdx.x + 1] = h1;
}

// ---------------- fp16 tensor-core GEMM -------------------------------------
// C[M,N] = A[M,K] @ W[N,K]^T + bias (+epilogue), A/W half, acc fp32.
// Block 128x128x32, 8 warps (2x4), warp tile 64x32, double-buffered, ldmatrix.
// EPI: 0 = bias only, 1 = bias + exact GELU, 2 = bias + fp32 residual

#define SLDH 40  // smem row stride in halves (32 + 8 pad): conflict-free ldmatrix

__device__ __forceinline__ unsigned s2u(const void* p) {
    unsigned r;
    asm("{ .reg .u64 t; cvta.to.shared.u64 t, %1; cvt.u32.u64 %0, t; }" : "=r"(r) : "l"(p));
    return r;
}

template <int EPI, typename OT>
__global__ __launch_bounds__(256, 2)
void hmma_gemm(const __half* __restrict__ A, const __half* __restrict__ W,
               const float* __restrict__ bias, const float* __restrict__ res,
               OT* __restrict__ C, int M, int N, int K) {
    extern __shared__ __half smh[];
    __half* As = smh;                    // [2][128][SLDH]
    __half* Bs = smh + 2 * 128 * SLDH;   // [2][128][SLDH]

    const int tid = threadIdx.x;
    const int lane = tid & 31, warp = tid >> 5;
    const int warp_m = warp >> 2, warp_n = warp & 3;
    const int grp = lane >> 2, tig = lane & 3;
    const int m0 = blockIdx.y * 128, n0 = blockIdx.x * 128;

    const __half* Ab = A + (size_t)m0 * K;
    const __half* Wb = W + (size_t)n0 * K;

    // ldmatrix per-lane address components
    const int aRow = warp_m * 64 + (lane & 7) + ((lane >> 3) & 1) * 8;
    const int aK   = (lane >> 4) * 8;
    const int bRow = warp_n * 32 + (lane & 7) + ((lane >> 4) & 1) * 8;
    const int bK   = ((lane >> 3) & 1) * 8;

    float acc[4][4][4];
#pragma unroll
    for (int mt = 0; mt < 4; mt++)
#pragma unroll
        for (int nt = 0; nt < 4; nt++)
#pragma unroll
            for (int i = 0; i < 4; i++) acc[mt][nt][i] = 0.f;

    // staging indices: 512 chunks of 8 halves (16B) per matrix per tile
    const int srow = tid >> 2;            // +128 for second iter? no: flat
    uint4 ra[2], rb[2];

    // ---- prefetch + store tile 0 ----
#pragma unroll
    for (int i = 0; i < 2; i++) {
        int flat = tid + i * 256;
        int row = flat >> 2, kc = (flat & 3) * 8;
        ra[i] = *reinterpret_cast<const uint4*>(Ab + (size_t)row * K + kc);
        rb[i] = *reinterpret_cast<const uint4*>(Wb + (size_t)row * K + kc);
    }
#pragma unroll
    for (int i = 0; i < 2; i++) {
        int flat = tid + i * 256;
        int row = flat >> 2, kc = (flat & 3) * 8;
        *reinterpret_cast<uint4*>(&As[row * SLDH + kc]) = ra[i];
        *reinterpret_cast<uint4*>(&Bs[row * SLDH + kc]) = rb[i];
    }
    __syncthreads();
    (void)srow;

    const int KIT = K >> 5;
    for (int it = 0; it < KIT; ++it) {
        if (it + 1 < KIT) {
            int k0 = (it + 1) << 5;
#pragma unroll
            for (int i = 0; i < 2; i++) {
                int flat = tid + i * 256;
                int row = flat >> 2, kc = (flat & 3) * 8;
                ra[i] = *reinterpret_cast<const uint4*>(Ab + (size_t)row * K + k0 + kc);
                rb[i] = *reinterpret_cast<const uint4*>(Wb + (size_t)row * K + k0 + kc);
            }
        }

        const __half* as = As + (it & 1) * 128 * SLDH;
        const __half* bs = Bs + (it & 1) * 128 * SLDH;

#pragma unroll
        for (int kb = 0; kb < 32; kb += 16) {
            unsigned af[4][4], bf[2][4];
#pragma unroll
            for (int mt = 0; mt < 4; mt++) {
                unsigned addr = s2u(&as[(aRow + mt * 16) * SLDH + kb + aK]);
                asm volatile("ldmatrix.sync.aligned.m8n8.x4.shared.b16 {%0,%1,%2,%3}, [%4];"
                             : "=r"(af[mt][0]), "=r"(af[mt][1]), "=r"(af[mt][2]), "=r"(af[mt][3])
                             : "r"(addr));
            }
#pragma unroll
            for (int ntp = 0; ntp < 2; ntp++) {
                unsigned addr = s2u(&bs[(bRow + ntp * 16) * SLDH + kb + bK]);
                asm volatile("ldmatrix.sync.aligned.m8n8.x4.shared.b16 {%0,%1,%2,%3}, [%4];"
                             : "=r"(bf[ntp][0]), "=r"(bf[ntp][1]), "=r"(bf[ntp][2]), "=r"(bf[ntp][3])
                             : "r"(addr));
            }
#pragma unroll
            for (int mt = 0; mt < 4; mt++)
#pragma unroll
                for (int nt = 0; nt < 4; nt++) {
                    const unsigned* bb = &bf[nt >> 1][(nt & 1) * 2];
                    asm volatile(
                        "mma.sync.aligned.m16n8k16.row.col.f32.f16.f16.f32 "
                        "{%0,%1,%2,%3}, {%4,%5,%6,%7}, {%8,%9}, {%0,%1,%2,%3};"
                        : "+f"(acc[mt][nt][0]), "+f"(acc[mt][nt][1]),
                          "+f"(acc[mt][nt][2]), "+f"(acc[mt][nt][3])
                        : "r"(af[mt][0]), "r"(af[mt][1]), "r"(af[mt][2]), "r"(af[mt][3]),
                          "r"(bb[0]), "r"(bb[1]));
                }
        }

        if (it + 1 < KIT) {
            __half* asn = As + ((it + 1) & 1) * 128 * SLDH;
            __half* bsn = Bs + ((it + 1) & 1) * 128 * SLDH;
#pragma unroll
            for (int i = 0; i < 2; i++) {
                int flat = tid + i * 256;
                int row = flat >> 2, kc = (flat & 3) * 8;
                *reinterpret_cast<uint4*>(&asn[row * SLDH + kc]) = ra[i];
                *reinterpret_cast<uint4*>(&bsn[row * SLDH + kc]) = rb[i];
            }
            __syncthreads();
        }
    }

    // ---- epilogue ----
#pragma unroll
    for (int mt = 0; mt < 4; mt++) {
#pragma unroll
        for (int half_ = 0; half_ < 2; half_++) {
            int r = m0 + warp_m * 64 + mt * 16 + grp + half_ * 8;
#pragma unroll
            for (int nt = 0; nt < 4; nt++) {
                int c = n0 + warp_n * 32 + nt * 8 + tig * 2;
                float v0 = acc[mt][nt][half_ * 2 + 0] + __ldg(&bias[c]);
                float v1 = acc[mt][nt][half_ * 2 + 1] + __ldg(&bias[c + 1]);
                if (EPI == 1) {
                    v0 = 0.5f * v0 * (1.0f + erff(v0 * 0.70710678118654752f));
                    v1 = 0.5f * v1 * (1.0f + erff(v1 * 0.70710678118654752f));
                }
                if (EPI == 2) {
                    const float2 rr = *reinterpret_cast<const float2*>(res + (size_t)r * N + c);
                    v0 += rr.x; v1 += rr.y;
                }
                if (sizeof(OT) == 2) {
                    *reinterpret_cast<__half2*>((__half*)C + (size_t)r * N + c) =
                        __floats2half2_rn(v0, v1);
                } else {
                    *reinterpret_cast<float2*>((float*)C + (size_t)r * N + c) =
                        make_float2(v0, v1);
                }
            }
        }
    }
}

// ---------------- Windowed attention (half in, half out, fp32 math) --------
__global__ __launch_bounds__(128)
void attn_kernel(const __half* __restrict__ qkv, __half* __restrict__ out) {
    __shared__ float ks[64 * 64];
    __shared__ float vs[64 * 64];
    int w = blockIdx.x, h = blockIdx.y, b = blockIdx.z;
    int q = threadIdx.x;
    size_t rowbase = ((size_t)b * SEQ + (size_t)w * WIN);

    const __half2* qrow = reinterpret_cast<const __half2*>(
        qkv + (rowbase + q) * (3 * DIMC) + h * HDIM);
    float4 qv[16];
#pragma unroll
    for (int i = 0; i < 16; i++) {
        float2 a = __half22float2(qrow[2 * i]);
        float2 bb = __half22float2(qrow[2 * i + 1]);
        qv[i] = make_float4(a.x, a.y, bb.x, bb.y);
    }

    float m = -1e30f, l = 0.f;
    float4 acc[16];
#pragma unroll
    for (int i = 0; i < 16; i++) acc[i] = make_float4(0.f, 0.f, 0.f, 0.f);

    for (int c = 0; c < 2; c++) {
        __syncthreads();
        {
            int r = threadIdx.x >> 1;
            int part = threadIdx.x & 1;
            const __half2* krow = reinterpret_cast<const __half2*>(
                qkv + (rowbase + c * 64 + r) * (3 * DIMC) + DIMC + h * HDIM + part * 32);
            const __half2* vrow = reinterpret_cast<const __half2*>(
                qkv + (rowbase + c * 64 + r) * (3 * DIMC) + 2 * DIMC + h * HDIM + part * 32);
            float* kd = &ks[r * 64 + part * 32];
            float* vd = &vs[r * 64 + part * 32];
#pragma unroll
            for (int i = 0; i < 16; i++) {
                float2 kf = __half22float2(krow[i]);
                float2 vf = __half22float2(vrow[i]);
                kd[2 * i] = kf.x; kd[2 * i + 1] = kf.y;
                vd[2 * i] = vf.x; vd[2 * i + 1] = vf.y;
            }
        }
        __syncthreads();

        for (int j = 0; j < 64; j++) {
            const float4* kj = reinterpret_cast<const float4*>(&ks[j * 64]);
            float s = 0.f;
#pragma unroll
            for (int i = 0; i < 16; i++) {
                float4 kk = kj[i];
                s += qv[i].x * kk.x + qv[i].y * kk.y + qv[i].z * kk.z + qv[i].w * kk.w;
            }
            s *= 0.125f;
            float mn = fmaxf(m, s);
            float corr = __expf(m - mn);
            float p = __expf(s - mn);
            l = l * corr + p;
            const float4* vj = reinterpret_cast<const float4*>(&vs[j * 64]);
#pragma unroll
            for (int i = 0; i < 16; i++) {
                float4 vv = vj[i];
                acc[i].x = acc[i].x * corr + p * vv.x;
                acc[i].y = acc[i].y * corr + p * vv.y;
                acc[i].z = acc[i].z * corr + p * vv.z;
                acc[i].w = acc[i].w * corr + p * vv.w;
            }
            m = mn;
        }
    }

    float inv = 1.f / l;
    __half2* orow = reinterpret_cast<__half2*>(out + (rowbase + q) * DIMC + h * HDIM);
#pragma unroll
    for (int i = 0; i < 16; i++) {
        float4 o = acc[i];
        orow[2 * i]     = __floats2half2_rn(o.x * inv, o.y * inv);
        orow[2 * i + 1] = __floats2half2_rn(o.z * inv, o.w * inv);
    }
}

// ---------------- launch --------------------------------------------------
#define GEMM_SMEM (4 * 128 * SLDH * 2)  // 2 buffers * (As+Bs) * 128 * SLDH halves

extern "C" void kernel_launch(void* const* d_in, const int* in_sizes, int n_in,
                              void* d_out, int out_size) {
    const float* x      = (const float*)d_in[0];
    const float* ln1_w  = (const float*)d_in[1];
    const float* ln1_b  = (const float*)d_in[2];
    const float* qkv_w  = (const float*)d_in[3];
    const float* qkv_b  = (const float*)d_in[4];
    const float* proj_w = (const float*)d_in[5];
    const float* proj_b = (const float*)d_in[6];
    const float* ln2_w  = (const float*)d_in[7];
    const float* ln2_b  = (const float*)d_in[8];
    const float* fc1_w  = (const float*)d_in[9];
    const float* fc1_b  = (const float*)d_in[10];
    const float* fc2_w  = (const float*)d_in[11];
    const float* fc2_b  = (const float*)d_in[12];
    float* out = (float*)d_out;

    __half *p_ln, *p_qkv, *p_attn, *p_g, *p_wqkv, *p_wproj, *p_wfc1, *p_wfc2;
    float* p_x2;
    cudaGetSymbolAddress((void**)&p_ln, g_ln);
    cudaGetSymbolAddress((void**)&p_qkv, g_qkv);
    cudaGetSymbolAddress((void**)&p_attn, g_attn);
    cudaGetSymbolAddress((void**)&p_x2, g_x2);
    cudaGetSymbolAddress((void**)&p_g, g_g);
    cudaGetSymbolAddress((void**)&p_wqkv, g_wqkv);
    cudaGetSymbolAddress((void**)&p_wproj, g_wproj);
    cudaGetSymbolAddress((void**)&p_wfc1, g_wfc1);
    cudaGetSymbolAddress((void**)&p_wfc2, g_wfc2);

    // 0. weight conversion (fp32 -> fp16)
    {
        int n;
        n = 3 * DIMC * DIMC / 4; f2h_kernel<<<(n + 255) / 256, 256>>>(qkv_w, p_wqkv, n);
        n = DIMC * DIMC / 4;     f2h_kernel<<<(n + 255) / 256, 256>>>(proj_w, p_wproj, n);
        n = MLPH * DIMC / 4;     f2h_kernel<<<(n + 255) / 256, 256>>>(fc1_w, p_wfc1, n);
        n = DIMC * MLPH / 4;     f2h_kernel<<<(n + 255) / 256, 256>>>(fc2_w, p_wfc2, n);
    }

    // 1. LN1
    ln_kernel<<<MROWS, 256>>>(x, ln1_w, ln1_b, p_ln);

    // 2. QKV (half out)
    {
        dim3 grid(3 * DIMC / 128, MROWS / 128);
        hmma_gemm<0, __half><<<grid, 256, GEMM_SMEM>>>(p_ln, p_wqkv, qkv_b, nullptr, p_qkv,
                                                       MROWS, 3 * DIMC, DIMC);
    }

    // 3. Windowed attention
    {
        dim3 grid(SEQ / WIN, HEADS, BATCH);
        attn_kernel<<<grid, 128>>>(p_qkv, p_attn);
    }

    // 4. Proj + residual (fp32 out)
    {
        dim3 grid(DIMC / 128, MROWS / 128);
        hmma_gemm<2, float><<<grid, 256, GEMM_SMEM>>>(p_attn, p_wproj, proj_b, x, p_x2,
                                                      MROWS, DIMC, DIMC);
    }

    // 5. LN2
    ln_kernel<<<MROWS, 256>>>(p_x2, ln2_w, ln2_b, p_ln);

    // 6. FC1 + GELU (half out)
    {
        dim3 grid(MLPH / 128, MROWS / 128);
        hmma_gemm<1, __half><<<grid, 256, GEMM_SMEM>>>(p_ln, p_wfc1, fc1_b, nullptr, p_g,
                                                       MROWS, MLPH, DIMC);
    }

    // 7. FC2 + residual (fp32 out)
    {
        dim3 grid(DIMC / 128, MROWS / 128);
        hmma_gemm<2, float><<<grid, 256, GEMM_SMEM>>>(p_g, p_wfc2, fc2_b, p_x2, out,
                                                      MROWS, DIMC, MLPH);
    }
}